// round 15
// baseline (speedup 1.0000x reference)
#include <cuda_runtime.h>
#include <cuda_fp16.h>
#include <cstdint>

// ---------------------------------------------------------------------------
// Problem constants
// ---------------------------------------------------------------------------
constexpr int kE = 32, kD = 2048, kF = 768, kT = 2048;
constexpr int k2F = 2 * kF;                       // 1536

constexpr int BM = 128, BN = 128, BK = 64;        // fp16: BK=64 (4 k16-steps)
constexpr int STAGES = 3;
constexpr int NTHREADS = 256;                     // 8 warps, 2(m) x 4(n), warp 64x32

constexpr int A_BYTES = BM * BK * 2;              // 16384
constexpr int B_BYTES = BK * BN * 2;              // 16384
constexpr int STAGE_BYTES = A_BYTES + B_BYTES;    // 32768
constexpr int SMEM_BYTES = STAGES * STAGE_BYTES;  // 98304 -> 2 CTA/SM

constexpr int KSPLIT = 8;                         // GEMM2 split-K over experts

// Scratch (device globals; uint4 arrays for 16B alignment)
__device__ uint4 g_Xh    [(size_t)kT * kD / 8];        // X fp16
__device__ uint4 g_Wguh  [(size_t)kE * kD * k2F / 8];  // Wgu fp16, gate/up col-interleaved
__device__ uint4 g_Wdh   [(size_t)kE * kF * kD / 8];   // Wd fp16
__device__ uint4 g_gatedh[(size_t)kE * kT * kF / 8];   // rw*up*silu(gate), fp16
__device__ float g_part  [(size_t)KSPLIT * kT * kD];   // split-K partials (8 x 16.8MB)

// ---------------------------------------------------------------------------
// helpers
// ---------------------------------------------------------------------------
__device__ __forceinline__ uint32_t smem_u32(const void* p) {
    uint32_t a;
    asm("{ .reg .u64 t; cvta.to.shared.u64 t, %1; cvt.u32.u64 %0, t; }"
        : "=r"(a) : "l"(p));
    return a;
}
__device__ __forceinline__ void cp16(uint32_t saddr, const void* g) {
    asm volatile("cp.async.cg.shared.global [%0], [%1], 16;" :: "r"(saddr), "l"(g));
}
#define CP_COMMIT() asm volatile("cp.async.commit_group;" ::: "memory")
#define CP_WAIT1()  asm volatile("cp.async.wait_group 1;" ::: "memory")

__device__ __forceinline__ void ldsm4(uint32_t* r, uint32_t addr) {
    asm volatile("ldmatrix.sync.aligned.m8n8.x4.shared.b16 {%0,%1,%2,%3}, [%4];"
        : "=r"(r[0]), "=r"(r[1]), "=r"(r[2]), "=r"(r[3]) : "r"(addr));
}
__device__ __forceinline__ void ldsm4t(uint32_t* r, uint32_t addr) {
    asm volatile("ldmatrix.sync.aligned.m8n8.x4.trans.shared.b16 {%0,%1,%2,%3}, [%4];"
        : "=r"(r[0]), "=r"(r[1]), "=r"(r[2]), "=r"(r[3]) : "r"(addr));
}
__device__ __forceinline__ void mma16(float* c, const uint32_t* a, const uint32_t* b) {
    asm volatile(
        "mma.sync.aligned.m16n8k16.row.col.f32.f16.f16.f32 "
        "{%0,%1,%2,%3}, {%4,%5,%6,%7}, {%8,%9}, {%0,%1,%2,%3};"
        : "+f"(c[0]), "+f"(c[1]), "+f"(c[2]), "+f"(c[3])
        : "r"(a[0]), "r"(a[1]), "r"(a[2]), "r"(a[3]), "r"(b[0]), "r"(b[1]));
}

__device__ __forceinline__ uint32_t pack2(float x, float y) {
    __half2 h = __floats2half2_rn(x, y);
    return *reinterpret_cast<uint32_t*>(&h);
}

// ---------------------------------------------------------------------------
// Per-thread fragment addressing (precomputed outside K loop)
// A tile: [BM][64] halves, 128B rows, 16B-unit swizzle u^=(row&7).
// B tile: [BK][128] halves, 256B rows, swizzle per 128B half.
// ---------------------------------------------------------------------------
struct Frag {
    int aRow[4];
    int aMask[4];
    int hi;
    int bOff[2];
    int g, tig, wm, wn;
};

__device__ __forceinline__ Frag make_frag(int tid) {
    Frag f;
    const int l = tid & 31, wid = tid >> 5;
    f.wm = (wid >> 2) * 64;
    f.wn = (wid & 3) * 32;
    f.g = l >> 2; f.tig = l & 3;
    f.hi = l >> 4;
    const int low8 = l & 7, seg8 = (l >> 3) & 1;
#pragma unroll
    for (int mi = 0; mi < 4; ++mi) {
        const int rA = f.wm + 16 * mi + low8 + 8 * seg8;
        f.aRow[mi] = rA * 128;
        f.aMask[mi] = rA & 7;
    }
#pragma unroll
    for (int p = 0; p < 2; ++p) {
        const int uB = (f.wn >> 3) + 2 * p + f.hi;
        f.bOff[p] = (l & 15) * 256 + ((uB >> 3) << 7) + ((((uB & 7) ^ low8)) << 4);
    }
    return f;
}

// Software-pipelined stage (k-step fragments prefetched one step ahead).
__device__ __forceinline__ void compute_stage(uint32_t As, uint32_t Bs,
                                              const Frag& f, float c[4][4][4]) {
    uint32_t a[2][4][4], rb[2][2][4];
#pragma unroll
    for (int mi = 0; mi < 4; ++mi)
        ldsm4(a[0][mi], As + f.aRow[mi] + ((f.hi ^ f.aMask[mi]) << 4));
#pragma unroll
    for (int p = 0; p < 2; ++p)
        ldsm4t(rb[0][p], Bs + f.bOff[p]);

#pragma unroll
    for (int ks = 0; ks < 4; ++ks) {
        const int cur = ks & 1, nxt = cur ^ 1;
        if (ks < 3) {
            const int kkU = 2 * (ks + 1);
#pragma unroll
            for (int mi = 0; mi < 4; ++mi)
                ldsm4(a[nxt][mi], As + f.aRow[mi] + (((kkU + f.hi) ^ f.aMask[mi]) << 4));
#pragma unroll
            for (int p = 0; p < 2; ++p)
                ldsm4t(rb[nxt][p], Bs + (16 * (ks + 1)) * 256 + f.bOff[p]);
        }
#pragma unroll
        for (int mi = 0; mi < 4; ++mi)
#pragma unroll
            for (int p = 0; p < 2; ++p) {
                mma16(c[mi][2 * p + 0], a[cur][mi], &rb[cur][p][0]);
                mma16(c[mi][2 * p + 1], a[cur][mi], &rb[cur][p][2]);
            }
    }
}

// cp.async destination offsets (byte), swizzled
__device__ __forceinline__ uint32_t a_dst(int row, int u) {        // u 0..7
    return (uint32_t)(row * 128 + ((u ^ (row & 7)) << 4));
}
__device__ __forceinline__ uint32_t b_dst(int row, int u) {        // u 0..15
    return (uint32_t)(row * 256 + ((u >> 3) << 7) + ((((u & 7) ^ (row & 7))) << 4));
}

// ---------------------------------------------------------------------------
// Pre-pass kernels — MLP=4: batch 4 independent 16B loads before any store.
// ---------------------------------------------------------------------------
__global__ __launch_bounds__(256) void prep_X(const float* __restrict__ X) {
    const size_t i0 = ((size_t)blockIdx.x * 256 + threadIdx.x) * 4;  // 4 uint4/thread
    float4 v[8];
#pragma unroll
    for (int q = 0; q < 4; ++q) {
        v[2 * q]     = *(const float4*)(X + (i0 + q) * 8);
        v[2 * q + 1] = *(const float4*)(X + (i0 + q) * 8 + 4);
    }
#pragma unroll
    for (int q = 0; q < 4; ++q) {
        uint4 o;
        o.x = pack2(v[2 * q].x, v[2 * q].y);     o.y = pack2(v[2 * q].z, v[2 * q].w);
        o.z = pack2(v[2 * q + 1].x, v[2 * q + 1].y); o.w = pack2(v[2 * q + 1].z, v[2 * q + 1].w);
        g_Xh[i0 + q] = o;
    }
}
// Wgu: interleave gate/up columns. Output col 2j = orig col j (gate),
// output col 2j+1 = orig col j+kF (up). Each thread: 16 consecutive gate floats
// + 16 up floats (4x16B loads each, batched) -> 4 output uint4.
__global__ __launch_bounds__(256) void prep_Wgu(const float* __restrict__ W) {
    constexpr int NG4 = k2F / 32;                             // 48 quad-groups/row
    const size_t i = (size_t)blockIdx.x * 256 + threadIdx.x;  // over E*D*NG4
    const int qg = (int)(i % NG4);
    const size_t row = i / NG4;
    const float* src = W + row * k2F + qg * 16;
    float4 gt[4], up[4];
#pragma unroll
    for (int q = 0; q < 4; ++q) gt[q] = *(const float4*)(src + q * 4);
#pragma unroll
    for (int q = 0; q < 4; ++q) up[q] = *(const float4*)(src + kF + q * 4);
    uint4* dst = g_Wguh + row * (k2F / 8) + qg * 4;
#pragma unroll
    for (int q = 0; q < 4; ++q) {
        uint4 o;
        o.x = pack2(gt[q].x, up[q].x); o.y = pack2(gt[q].y, up[q].y);
        o.z = pack2(gt[q].z, up[q].z); o.w = pack2(gt[q].w, up[q].w);
        dst[q] = o;
    }
}
__global__ __launch_bounds__(256) void prep_Wd(const float* __restrict__ W) {
    const size_t i0 = ((size_t)blockIdx.x * 256 + threadIdx.x) * 4;
    float4 v[8];
#pragma unroll
    for (int q = 0; q < 4; ++q) {
        v[2 * q]     = *(const float4*)(W + (i0 + q) * 8);
        v[2 * q + 1] = *(const float4*)(W + (i0 + q) * 8 + 4);
    }
#pragma unroll
    for (int q = 0; q < 4; ++q) {
        uint4 o;
        o.x = pack2(v[2 * q].x, v[2 * q].y);     o.y = pack2(v[2 * q].z, v[2 * q].w);
        o.z = pack2(v[2 * q + 1].x, v[2 * q + 1].y); o.w = pack2(v[2 * q + 1].z, v[2 * q + 1].w);
        g_Wdh[i0 + q] = o;
    }
}

// ---------------------------------------------------------------------------
// GEMM1 (fused): C = Xh @ Wguh (gate/up interleaved cols); epilogue computes
// fp16(rw*up*silu(gate)), stages through smem, stores coalesced 16B chunks.
// grid (16, 12, 32), 256 threads, 32 K-iters of BK=64.
// ---------------------------------------------------------------------------
constexpr int EP_LD = 72;   // halves per staging row (144B; pad kills bank alias)

__global__ __launch_bounds__(NTHREADS, 2)
void moe_gemm1(const float* __restrict__ RW) {
    extern __shared__ char smem[];
    const int tid = threadIdx.x;
    const int m0 = blockIdx.x * BM, n0 = blockIdx.y * BN, e = blockIdx.z;
    const uint32_t sb = smem_u32(smem);

    const __half* Xh = (const __half*)g_Xh;
    const __half* We = (const __half*)g_Wguh + (size_t)e * kD * k2F;

    const int arow = tid >> 1, au = (tid & 1) * 4;
    const int brow = tid >> 2, bu = (tid & 3) * 4;
    const __half* gA = Xh + (size_t)(m0 + arow) * kD + au * 8;
    const __half* gB = We + (size_t)brow * k2F + n0 + bu * 8;

    uint32_t aD[4], bD[4];
#pragma unroll
    for (int q = 0; q < 4; ++q) {
        aD[q] = a_dst(arow, au + q);
        bD[q] = b_dst(brow, bu + q);
    }

    const Frag f = make_frag(tid);
    float c[4][4][4];
#pragma unroll
    for (int i = 0; i < 4; ++i)
#pragma unroll
        for (int j = 0; j < 4; ++j)
#pragma unroll
            for (int q = 0; q < 4; ++q) c[i][j][q] = 0.0f;

    constexpr int ITERS = kD / BK;   // 32

    auto issue = [&](int it) {
        const uint32_t st = sb + (it % STAGES) * STAGE_BYTES;
        const int k0 = it * BK;
#pragma unroll
        for (int q = 0; q < 4; ++q)
            cp16(st + aD[q], gA + k0 + q * 8);
#pragma unroll
        for (int q = 0; q < 4; ++q)
            cp16(st + A_BYTES + bD[q], gB + (size_t)k0 * k2F + q * 8);
    };

    issue(0); CP_COMMIT();
    issue(1); CP_COMMIT();

    for (int it = 0; it < ITERS; ++it) {
        CP_WAIT1();
        __syncthreads();
        if (it + 2 < ITERS) issue(it + 2);
        CP_COMMIT();
        const uint32_t st = sb + (it % STAGES) * STAGE_BYTES;
        compute_stage(st, st + A_BYTES, f, c);
    }

    // ---- Fused epilogue, smem-staged for coalesced stores ----
    __syncthreads();
    __half* s_ep = (__half*)smem;            // [128 rows][EP_LD halves]
#pragma unroll
    for (int mi = 0; mi < 4; ++mi) {
        const int row0 = f.wm + 16 * mi + f.g;
        const int row1 = row0 + 8;
        const float rw0 = RW[(size_t)(m0 + row0) * kE + e];
        const float rw1 = RW[(size_t)(m0 + row1) * kE + e];
#pragma unroll
        for (int nj = 0; nj < 4; ++nj) {
            const int fl = (f.wn >> 1) + 4 * nj + f.tig;
            const float gt0 = c[mi][nj][0], up0 = c[mi][nj][1];
            const float gt1 = c[mi][nj][2], up1 = c[mi][nj][3];
            s_ep[row0 * EP_LD + fl] =
                __float2half_rn(rw0 * up0 * (gt0 / (1.0f + __expf(-gt0))));
            s_ep[row1 * EP_LD + fl] =
                __float2half_rn(rw1 * up1 * (gt1 / (1.0f + __expf(-gt1))));
        }
    }
    __syncthreads();

    const int erow = tid >> 1, eseg = (tid & 1) * 32;
    const int f0 = n0 >> 1;
    const uint4* src = (const uint4*)(s_ep + erow * EP_LD + eseg);
    uint4* dst = (uint4*)((__half*)g_gatedh +
                          ((size_t)e * kT + m0 + erow) * kF + f0 + eseg);
#pragma unroll
    for (int q = 0; q < 4; ++q) dst[q] = src[q];
}

// ---------------------------------------------------------------------------
// GEMM2 (split-K x8 over experts): z handles experts [4z, 4z+4) -> g_part[z].
// grid (16, 16, 8), 256 threads, 48 K-iters of BK=64.
// ---------------------------------------------------------------------------
__global__ __launch_bounds__(NTHREADS, 2)
void moe_gemm2() {
    extern __shared__ char smem[];
    const int tid = threadIdx.x;
    const int m0 = blockIdx.x * BM, n0 = blockIdx.y * BN;
    const int ez = blockIdx.z * (kE / KSPLIT);
    const uint32_t sb = smem_u32(smem);

    const __half* Ah = (const __half*)g_gatedh;
    const __half* Wh = (const __half*)g_Wdh;

    const int arow = tid >> 1, au = (tid & 1) * 4;
    const int brow = tid >> 2, bu = (tid & 3) * 4;

    uint32_t aD[4], bD[4];
#pragma unroll
    for (int q = 0; q < 4; ++q) {
        aD[q] = a_dst(arow, au + q);
        bD[q] = b_dst(brow, bu + q);
    }

    const Frag f = make_frag(tid);
    float c[4][4][4];
#pragma unroll
    for (int i = 0; i < 4; ++i)
#pragma unroll
        for (int j = 0; j < 4; ++j)
#pragma unroll
            for (int q = 0; q < 4; ++q) c[i][j][q] = 0.0f;

    constexpr int IPEX  = kF / BK;                       // 12
    constexpr int ITERS = (kE / KSPLIT) * IPEX;          // 48

    auto issue = [&](int it) {
        const uint32_t st = sb + (it % STAGES) * STAGE_BYTES;
        const int e   = ez + it / IPEX;
        const int kin = (it % IPEX) * BK;
        const __half* gA = Ah + ((size_t)e * kT + m0 + arow) * kF + kin + au * 8;
        const __half* gB = Wh + ((size_t)e * kF + kin + brow) * kD + n0 + bu * 8;
#pragma unroll
        for (int q = 0; q < 4; ++q)
            cp16(st + aD[q], gA + q * 8);
#pragma unroll
        for (int q = 0; q < 4; ++q)
            cp16(st + A_BYTES + bD[q], gB + q * 8);
    };

    issue(0); CP_COMMIT();
    issue(1); CP_COMMIT();

    for (int it = 0; it < ITERS; ++it) {
        CP_WAIT1();
        __syncthreads();
        if (it + 2 < ITERS) issue(it + 2);
        CP_COMMIT();
        const uint32_t st = sb + (it % STAGES) * STAGE_BYTES;
        compute_stage(st, st + A_BYTES, f, c);
    }

    float* Cp = g_part + (size_t)blockIdx.z * kT * kD + (size_t)m0 * kD + n0;
#pragma unroll
    for (int mi = 0; mi < 4; ++mi)
#pragma unroll
        for (int nj = 0; nj < 4; ++nj) {
            const int r0 = f.wm + 16 * mi + f.g;
            const int cc = f.wn + 8 * nj + 2 * f.tig;
            *(float2*)(Cp + (size_t)r0 * kD + cc) = make_float2(c[mi][nj][0], c[mi][nj][1]);
            *(float2*)(Cp + (size_t)(r0 + 8) * kD + cc) = make_float2(c[mi][nj][2], c[mi][nj][3]);
        }
}

// Combine split-K partials: Out = sum_z g_part[z]  (batched loads, MLP-friendly)
__global__ __launch_bounds__(256)
void moe_add(float* __restrict__ Out) {
    const size_t i4 = ((size_t)blockIdx.x * 256 + threadIdx.x) * 4;
    float4 v[KSPLIT];
#pragma unroll
    for (int z = 0; z < KSPLIT; ++z)
        v[z] = *(const float4*)(g_part + (size_t)z * kT * kD + i4);
    float4 s = v[0];
#pragma unroll
    for (int z = 1; z < KSPLIT; ++z) {
        s.x += v[z].x; s.y += v[z].y; s.z += v[z].z; s.w += v[z].w;
    }
    *(float4*)(Out + i4) = s;
}

// ---------------------------------------------------------------------------
// kernel_launch
//   0: hidden_states fp32 [T,D]   1: routing_weights fp32 [T,E]
//   2: router_indices (unused)    3: gate_up_proj fp32 [E,D,2F]
//   4: down_proj fp32 [E,F,D]     out: fp32 [T,D]
// ---------------------------------------------------------------------------
extern "C" void kernel_launch(void* const* d_in, const int* in_sizes, int n_in,
                              void* d_out, int out_size)
{
    const float* X   = (const float*)d_in[0];
    const float* RW  = (const float*)d_in[1];
    const float* Wgu = (const float*)d_in[3];
    const float* Wdn = (const float*)d_in[4];
    float* Out = (float*)d_out;

    cudaFuncSetAttribute(moe_gemm1, cudaFuncAttributeMaxDynamicSharedMemorySize, SMEM_BYTES);
    cudaFuncSetAttribute(moe_gemm2, cudaFuncAttributeMaxDynamicSharedMemorySize, SMEM_BYTES);

    prep_X<<<(int)(((size_t)kT * kD / 32) / 256), 256>>>(X);                   // 512
    prep_Wgu<<<(int)(((size_t)kE * kD * (k2F / 32)) / 256), 256>>>(Wgu);       // 12288
    prep_Wd<<<(int)(((size_t)kE * kF * kD / 32) / 256), 256>>>(Wdn);           // 6144

    moe_gemm1<<<dim3(kT / BM, k2F / BN, kE), NTHREADS, SMEM_BYTES>>>(RW);      // (16,12,32)

    moe_gemm2<<<dim3(kT / BM, kD / BN, KSPLIT), NTHREADS, SMEM_BYTES>>>();     // (16,16,8)
    moe_add<<<(int)(((size_t)kT * kD / 4) / 256), 256>>>(Out);                 // 4096
}

// round 16
// speedup vs baseline: 1.0133x; 1.0133x over previous
#include <cuda_runtime.h>
#include <cuda_fp16.h>
#include <cstdint>

// ---------------------------------------------------------------------------
// Problem constants
// ---------------------------------------------------------------------------
constexpr int kE = 32, kD = 2048, kF = 768, kT = 2048;
constexpr int k2F = 2 * kF;                       // 1536

constexpr int BM = 128, BN = 128, BK = 64;        // fp16: BK=64 (4 k16-steps)
constexpr int STAGES = 3;
constexpr int NTHREADS = 256;                     // 8 warps, 2(m) x 4(n), warp 64x32

constexpr int A_BYTES = BM * BK * 2;              // 16384
constexpr int B_BYTES = BK * BN * 2;              // 16384
constexpr int STAGE_BYTES = A_BYTES + B_BYTES;    // 32768
constexpr int SMEM_BYTES = STAGES * STAGE_BYTES;  // 98304 -> 2 CTA/SM

constexpr int KSPLIT = 8;                         // GEMM2 split-K over experts

// Scratch (device globals; uint4 arrays for 16B alignment)
__device__ uint4 g_Xh    [(size_t)kT * kD / 8];        // X fp16
__device__ uint4 g_Wguh  [(size_t)kE * kD * k2F / 8];  // Wgu fp16, gate/up col-interleaved
__device__ uint4 g_Wdh   [(size_t)kE * kF * kD / 8];   // Wd fp16
__device__ uint4 g_gatedh[(size_t)kE * kT * kF / 8];   // rw*up*silu(gate), fp16
__device__ float g_part  [(size_t)KSPLIT * kT * kD];   // split-K partials (8 x 16.8MB)

// ---------------------------------------------------------------------------
// helpers
// ---------------------------------------------------------------------------
__device__ __forceinline__ uint32_t smem_u32(const void* p) {
    uint32_t a;
    asm("{ .reg .u64 t; cvta.to.shared.u64 t, %1; cvt.u32.u64 %0, t; }"
        : "=r"(a) : "l"(p));
    return a;
}
__device__ __forceinline__ void cp16(uint32_t saddr, const void* g) {
    asm volatile("cp.async.cg.shared.global [%0], [%1], 16;" :: "r"(saddr), "l"(g));
}
#define CP_COMMIT() asm volatile("cp.async.commit_group;" ::: "memory")
#define CP_WAIT1()  asm volatile("cp.async.wait_group 1;" ::: "memory")

__device__ __forceinline__ void ldsm4(uint32_t* r, uint32_t addr) {
    asm volatile("ldmatrix.sync.aligned.m8n8.x4.shared.b16 {%0,%1,%2,%3}, [%4];"
        : "=r"(r[0]), "=r"(r[1]), "=r"(r[2]), "=r"(r[3]) : "r"(addr));
}
__device__ __forceinline__ void ldsm4t(uint32_t* r, uint32_t addr) {
    asm volatile("ldmatrix.sync.aligned.m8n8.x4.trans.shared.b16 {%0,%1,%2,%3}, [%4];"
        : "=r"(r[0]), "=r"(r[1]), "=r"(r[2]), "=r"(r[3]) : "r"(addr));
}
__device__ __forceinline__ void mma16(float* c, const uint32_t* a, const uint32_t* b) {
    asm volatile(
        "mma.sync.aligned.m16n8k16.row.col.f32.f16.f16.f32 "
        "{%0,%1,%2,%3}, {%4,%5,%6,%7}, {%8,%9}, {%0,%1,%2,%3};"
        : "+f"(c[0]), "+f"(c[1]), "+f"(c[2]), "+f"(c[3])
        : "r"(a[0]), "r"(a[1]), "r"(a[2]), "r"(a[3]), "r"(b[0]), "r"(b[1]));
}

__device__ __forceinline__ uint32_t pack2(float x, float y) {
    __half2 h = __floats2half2_rn(x, y);
    return *reinterpret_cast<uint32_t*>(&h);
}

// ---------------------------------------------------------------------------
// Per-thread fragment addressing (precomputed outside K loop)
// A tile: [BM][64] halves, 128B rows, 16B-unit swizzle u^=(row&7).
// B tile: [BK][128] halves, 256B rows, swizzle per 128B half.
// ---------------------------------------------------------------------------
struct Frag {
    int aRow[4];
    int aMask[4];
    int hi;
    int bOff[2];
    int g, tig, wm, wn;
};

__device__ __forceinline__ Frag make_frag(int tid) {
    Frag f;
    const int l = tid & 31, wid = tid >> 5;
    f.wm = (wid >> 2) * 64;
    f.wn = (wid & 3) * 32;
    f.g = l >> 2; f.tig = l & 3;
    f.hi = l >> 4;
    const int low8 = l & 7, seg8 = (l >> 3) & 1;
#pragma unroll
    for (int mi = 0; mi < 4; ++mi) {
        const int rA = f.wm + 16 * mi + low8 + 8 * seg8;
        f.aRow[mi] = rA * 128;
        f.aMask[mi] = rA & 7;
    }
#pragma unroll
    for (int p = 0; p < 2; ++p) {
        const int uB = (f.wn >> 3) + 2 * p + f.hi;
        f.bOff[p] = (l & 15) * 256 + ((uB >> 3) << 7) + ((((uB & 7) ^ low8)) << 4);
    }
    return f;
}

// Software-pipelined stage (k-step fragments prefetched one step ahead).
__device__ __forceinline__ void compute_stage(uint32_t As, uint32_t Bs,
                                              const Frag& f, float c[4][4][4]) {
    uint32_t a[2][4][4], rb[2][2][4];
#pragma unroll
    for (int mi = 0; mi < 4; ++mi)
        ldsm4(a[0][mi], As + f.aRow[mi] + ((f.hi ^ f.aMask[mi]) << 4));
#pragma unroll
    for (int p = 0; p < 2; ++p)
        ldsm4t(rb[0][p], Bs + f.bOff[p]);

#pragma unroll
    for (int ks = 0; ks < 4; ++ks) {
        const int cur = ks & 1, nxt = cur ^ 1;
        if (ks < 3) {
            const int kkU = 2 * (ks + 1);
#pragma unroll
            for (int mi = 0; mi < 4; ++mi)
                ldsm4(a[nxt][mi], As + f.aRow[mi] + (((kkU + f.hi) ^ f.aMask[mi]) << 4));
#pragma unroll
            for (int p = 0; p < 2; ++p)
                ldsm4t(rb[nxt][p], Bs + (16 * (ks + 1)) * 256 + f.bOff[p]);
        }
#pragma unroll
        for (int mi = 0; mi < 4; ++mi)
#pragma unroll
            for (int p = 0; p < 2; ++p) {
                mma16(c[mi][2 * p + 0], a[cur][mi], &rb[cur][p][0]);
                mma16(c[mi][2 * p + 1], a[cur][mi], &rb[cur][p][2]);
            }
    }
}

// cp.async destination offsets (byte), swizzled
__device__ __forceinline__ uint32_t a_dst(int row, int u) {        // u 0..7
    return (uint32_t)(row * 128 + ((u ^ (row & 7)) << 4));
}
__device__ __forceinline__ uint32_t b_dst(int row, int u) {        // u 0..15
    return (uint32_t)(row * 256 + ((u >> 3) << 7) + ((((u & 7) ^ (row & 7))) << 4));
}

// ---------------------------------------------------------------------------
// Pre-pass kernels (simple one-load form — measured faster than MLP-batched)
// ---------------------------------------------------------------------------
__device__ __forceinline__ void conv8(const float* src, uint4* dst) {
    const float4 a = *(const float4*)(src);
    const float4 b = *(const float4*)(src + 4);
    uint4 o;
    o.x = pack2(a.x, a.y); o.y = pack2(a.z, a.w);
    o.z = pack2(b.x, b.y); o.w = pack2(b.z, b.w);
    *dst = o;
}
__global__ __launch_bounds__(256) void prep_X(const float* __restrict__ X) {
    const size_t i = (size_t)blockIdx.x * 256 + threadIdx.x;
    conv8(X + i * 8, g_Xh + i);
}
// Wgu: interleave gate/up columns. Output col 2j = orig col j (gate),
// output col 2j+1 = orig col j+kF (up).
__global__ __launch_bounds__(256) void prep_Wgu(const float* __restrict__ W) {
    const size_t i = (size_t)blockIdx.x * 256 + threadIdx.x;  // over E*D*2F/8
    constexpr int NG = k2F / 8;                               // 192 groups/row
    const int grp = (int)(i % NG);
    const size_t row = i / NG;
    const float* src = W + row * k2F;
    const int j0 = grp * 4;
    const float4 gt = *(const float4*)(src + j0);
    const float4 up = *(const float4*)(src + kF + j0);
    uint4 o;
    o.x = pack2(gt.x, up.x); o.y = pack2(gt.y, up.y);
    o.z = pack2(gt.z, up.z); o.w = pack2(gt.w, up.w);
    g_Wguh[i] = o;
}
__global__ __launch_bounds__(256) void prep_Wd(const float* __restrict__ W) {
    const size_t i = (size_t)blockIdx.x * 256 + threadIdx.x;
    conv8(W + i * 8, g_Wdh + i);
}

// ---------------------------------------------------------------------------
// GEMM1 (fused): C = Xh @ Wguh (gate/up interleaved cols); epilogue computes
// fp16(rw*up*silu(gate)), stages through smem, stores coalesced 16B chunks.
// grid (16, 12, 32), 256 threads, 32 K-iters of BK=64.
// ---------------------------------------------------------------------------
constexpr int EP_LD = 72;   // halves per staging row (144B; pad kills bank alias)

__global__ __launch_bounds__(NTHREADS, 2)
void moe_gemm1(const float* __restrict__ RW) {
    extern __shared__ char smem[];
    const int tid = threadIdx.x;
    const int m0 = blockIdx.x * BM, n0 = blockIdx.y * BN, e = blockIdx.z;
    const uint32_t sb = smem_u32(smem);

    const __half* Xh = (const __half*)g_Xh;
    const __half* We = (const __half*)g_Wguh + (size_t)e * kD * k2F;

    const int arow = tid >> 1, au = (tid & 1) * 4;
    const int brow = tid >> 2, bu = (tid & 3) * 4;
    const __half* gA = Xh + (size_t)(m0 + arow) * kD + au * 8;
    const __half* gB = We + (size_t)brow * k2F + n0 + bu * 8;

    uint32_t aD[4], bD[4];
#pragma unroll
    for (int q = 0; q < 4; ++q) {
        aD[q] = a_dst(arow, au + q);
        bD[q] = b_dst(brow, bu + q);
    }

    const Frag f = make_frag(tid);
    float c[4][4][4];
#pragma unroll
    for (int i = 0; i < 4; ++i)
#pragma unroll
        for (int j = 0; j < 4; ++j)
#pragma unroll
            for (int q = 0; q < 4; ++q) c[i][j][q] = 0.0f;

    constexpr int ITERS = kD / BK;   // 32

    auto issue = [&](int it) {
        const uint32_t st = sb + (it % STAGES) * STAGE_BYTES;
        const int k0 = it * BK;
#pragma unroll
        for (int q = 0; q < 4; ++q)
            cp16(st + aD[q], gA + k0 + q * 8);
#pragma unroll
        for (int q = 0; q < 4; ++q)
            cp16(st + A_BYTES + bD[q], gB + (size_t)k0 * k2F + q * 8);
    };

    issue(0); CP_COMMIT();
    issue(1); CP_COMMIT();

    for (int it = 0; it < ITERS; ++it) {
        CP_WAIT1();
        __syncthreads();
        if (it + 2 < ITERS) issue(it + 2);
        CP_COMMIT();
        const uint32_t st = sb + (it % STAGES) * STAGE_BYTES;
        compute_stage(st, st + A_BYTES, f, c);
    }

    // ---- Fused epilogue, smem-staged for coalesced stores ----
    __syncthreads();
    __half* s_ep = (__half*)smem;            // [128 rows][EP_LD halves]
#pragma unroll
    for (int mi = 0; mi < 4; ++mi) {
        const int row0 = f.wm + 16 * mi + f.g;
        const int row1 = row0 + 8;
        const float rw0 = RW[(size_t)(m0 + row0) * kE + e];
        const float rw1 = RW[(size_t)(m0 + row1) * kE + e];
#pragma unroll
        for (int nj = 0; nj < 4; ++nj) {
            const int fl = (f.wn >> 1) + 4 * nj + f.tig;
            const float gt0 = c[mi][nj][0], up0 = c[mi][nj][1];
            const float gt1 = c[mi][nj][2], up1 = c[mi][nj][3];
            s_ep[row0 * EP_LD + fl] =
                __float2half_rn(rw0 * up0 * (gt0 / (1.0f + __expf(-gt0))));
            s_ep[row1 * EP_LD + fl] =
                __float2half_rn(rw1 * up1 * (gt1 / (1.0f + __expf(-gt1))));
        }
    }
    __syncthreads();

    const int erow = tid >> 1, eseg = (tid & 1) * 32;
    const int f0 = n0 >> 1;
    const uint4* src = (const uint4*)(s_ep + erow * EP_LD + eseg);
    uint4* dst = (uint4*)((__half*)g_gatedh +
                          ((size_t)e * kT + m0 + erow) * kF + f0 + eseg);
#pragma unroll
    for (int q = 0; q < 4; ++q) dst[q] = src[q];
}

// ---------------------------------------------------------------------------
// GEMM2 (split-K x8 over experts): z handles experts [4z, 4z+4) -> g_part[z].
// grid (16, 16, 8), 256 threads, 48 K-iters of BK=64.
// ---------------------------------------------------------------------------
__global__ __launch_bounds__(NTHREADS, 2)
void moe_gemm2() {
    extern __shared__ char smem[];
    const int tid = threadIdx.x;
    const int m0 = blockIdx.x * BM, n0 = blockIdx.y * BN;
    const int ez = blockIdx.z * (kE / KSPLIT);
    const uint32_t sb = smem_u32(smem);

    const __half* Ah = (const __half*)g_gatedh;
    const __half* Wh = (const __half*)g_Wdh;

    const int arow = tid >> 1, au = (tid & 1) * 4;
    const int brow = tid >> 2, bu = (tid & 3) * 4;

    uint32_t aD[4], bD[4];
#pragma unroll
    for (int q = 0; q < 4; ++q) {
        aD[q] = a_dst(arow, au + q);
        bD[q] = b_dst(brow, bu + q);
    }

    const Frag f = make_frag(tid);
    float c[4][4][4];
#pragma unroll
    for (int i = 0; i < 4; ++i)
#pragma unroll
        for (int j = 0; j < 4; ++j)
#pragma unroll
            for (int q = 0; q < 4; ++q) c[i][j][q] = 0.0f;

    constexpr int IPEX  = kF / BK;                       // 12
    constexpr int ITERS = (kE / KSPLIT) * IPEX;          // 48

    auto issue = [&](int it) {
        const uint32_t st = sb + (it % STAGES) * STAGE_BYTES;
        const int e   = ez + it / IPEX;
        const int kin = (it % IPEX) * BK;
        const __half* gA = Ah + ((size_t)e * kT + m0 + arow) * kF + kin + au * 8;
        const __half* gB = Wh + ((size_t)e * kF + kin + brow) * kD + n0 + bu * 8;
#pragma unroll
        for (int q = 0; q < 4; ++q)
            cp16(st + aD[q], gA + q * 8);
#pragma unroll
        for (int q = 0; q < 4; ++q)
            cp16(st + A_BYTES + bD[q], gB + q * 8);
    };

    issue(0); CP_COMMIT();
    issue(1); CP_COMMIT();

    for (int it = 0; it < ITERS; ++it) {
        CP_WAIT1();
        __syncthreads();
        if (it + 2 < ITERS) issue(it + 2);
        CP_COMMIT();
        const uint32_t st = sb + (it % STAGES) * STAGE_BYTES;
        compute_stage(st, st + A_BYTES, f, c);
    }

    float* Cp = g_part + (size_t)blockIdx.z * kT * kD + (size_t)m0 * kD + n0;
#pragma unroll
    for (int mi = 0; mi < 4; ++mi)
#pragma unroll
        for (int nj = 0; nj < 4; ++nj) {
            const int r0 = f.wm + 16 * mi + f.g;
            const int cc = f.wn + 8 * nj + 2 * f.tig;
            *(float2*)(Cp + (size_t)r0 * kD + cc) = make_float2(c[mi][nj][0], c[mi][nj][1]);
            *(float2*)(Cp + (size_t)(r0 + 8) * kD + cc) = make_float2(c[mi][nj][2], c[mi][nj][3]);
        }
}

// Combine split-K partials: Out = sum_z g_part[z]
__global__ __launch_bounds__(256)
void moe_add(float* __restrict__ Out) {
    const size_t i4 = ((size_t)blockIdx.x * 256 + threadIdx.x) * 4;
    float4 s = *(const float4*)(g_part + i4);
#pragma unroll
    for (int z = 1; z < KSPLIT; ++z) {
        const float4 b = *(const float4*)(g_part + (size_t)z * kT * kD + i4);
        s.x += b.x; s.y += b.y; s.z += b.z; s.w += b.w;
    }
    *(float4*)(Out + i4) = s;
}

// ---------------------------------------------------------------------------
// kernel_launch
//   0: hidden_states fp32 [T,D]   1: routing_weights fp32 [T,E]
//   2: router_indices (unused)    3: gate_up_proj fp32 [E,D,2F]
//   4: down_proj fp32 [E,F,D]     out: fp32 [T,D]
// ---------------------------------------------------------------------------
extern "C" void kernel_launch(void* const* d_in, const int* in_sizes, int n_in,
                              void* d_out, int out_size)
{
    const float* X   = (const float*)d_in[0];
    const float* RW  = (const float*)d_in[1];
    const float* Wgu = (const float*)d_in[3];
    const float* Wdn = (const float*)d_in[4];
    float* Out = (float*)d_out;

    cudaFuncSetAttribute(moe_gemm1, cudaFuncAttributeMaxDynamicSharedMemorySize, SMEM_BYTES);
    cudaFuncSetAttribute(moe_gemm2, cudaFuncAttributeMaxDynamicSharedMemorySize, SMEM_BYTES);

    prep_X<<<(int)(((size_t)kT * kD / 8) / 256), 256>>>(X);                    // 2048
    prep_Wgu<<<(int)(((size_t)kE * kD * k2F / 8) / 256), 256>>>(Wgu);          // 49152
    prep_Wd<<<(int)(((size_t)kE * kF * kD / 8) / 256), 256>>>(Wdn);            // 24576

    moe_gemm1<<<dim3(kT / BM, k2F / BN, kE), NTHREADS, SMEM_BYTES>>>(RW);      // (16,12,32)

    moe_gemm2<<<dim3(kT / BM, kD / BN, KSPLIT), NTHREADS, SMEM_BYTES>>>();     // (16,16,8)
    moe_add<<<(int)(((size_t)kT * kD / 4) / 256), 256>>>(Out);                 // 4096
}

// round 17
// speedup vs baseline: 1.0151x; 1.0018x over previous
#include <cuda_runtime.h>
#include <cuda_fp16.h>
#include <cstdint>

// ---------------------------------------------------------------------------
// Problem constants
// ---------------------------------------------------------------------------
constexpr int kE = 32, kD = 2048, kF = 768, kT = 2048;
constexpr int k2F = 2 * kF;                       // 1536

constexpr int BM = 128, BN = 128, BK = 64;        // fp16: BK=64 (4 k16-steps)
constexpr int STAGES = 3;
constexpr int NTHREADS = 256;                     // 8 warps, 2(m) x 4(n), warp 64x32

constexpr int A_BYTES = BM * BK * 2;              // 16384
constexpr int B_BYTES = BK * BN * 2;              // 16384
constexpr int STAGE_BYTES = A_BYTES + B_BYTES;    // 32768
constexpr int SMEM_BYTES = STAGES * STAGE_BYTES;  // 98304 -> 2 CTA/SM

constexpr int KSPLIT = 8;                         // GEMM2 split-K over experts

// Scratch (device globals; uint4 arrays for 16B alignment)
__device__ uint4 g_Xh    [(size_t)kT * kD / 8];        // X fp16
__device__ uint4 g_Wguh  [(size_t)kE * kD * k2F / 8];  // Wgu fp16, gate/up col-interleaved
__device__ uint4 g_Wdh   [(size_t)kE * kF * kD / 8];   // Wd fp16
__device__ uint4 g_gatedh[(size_t)kE * kT * kF / 8];   // rw*up*silu(gate), fp16

// ---------------------------------------------------------------------------
// helpers
// ---------------------------------------------------------------------------
__device__ __forceinline__ uint32_t smem_u32(const void* p) {
    uint32_t a;
    asm("{ .reg .u64 t; cvta.to.shared.u64 t, %1; cvt.u32.u64 %0, t; }"
        : "=r"(a) : "l"(p));
    return a;
}
__device__ __forceinline__ void cp16(uint32_t saddr, const void* g) {
    asm volatile("cp.async.cg.shared.global [%0], [%1], 16;" :: "r"(saddr), "l"(g));
}
#define CP_COMMIT() asm volatile("cp.async.commit_group;" ::: "memory")
#define CP_WAIT1()  asm volatile("cp.async.wait_group 1;" ::: "memory")

__device__ __forceinline__ void ldsm4(uint32_t* r, uint32_t addr) {
    asm volatile("ldmatrix.sync.aligned.m8n8.x4.shared.b16 {%0,%1,%2,%3}, [%4];"
        : "=r"(r[0]), "=r"(r[1]), "=r"(r[2]), "=r"(r[3]) : "r"(addr));
}
__device__ __forceinline__ void ldsm4t(uint32_t* r, uint32_t addr) {
    asm volatile("ldmatrix.sync.aligned.m8n8.x4.trans.shared.b16 {%0,%1,%2,%3}, [%4];"
        : "=r"(r[0]), "=r"(r[1]), "=r"(r[2]), "=r"(r[3]) : "r"(addr));
}
__device__ __forceinline__ void mma16(float* c, const uint32_t* a, const uint32_t* b) {
    asm volatile(
        "mma.sync.aligned.m16n8k16.row.col.f32.f16.f16.f32 "
        "{%0,%1,%2,%3}, {%4,%5,%6,%7}, {%8,%9}, {%0,%1,%2,%3};"
        : "+f"(c[0]), "+f"(c[1]), "+f"(c[2]), "+f"(c[3])
        : "r"(a[0]), "r"(a[1]), "r"(a[2]), "r"(a[3]), "r"(b[0]), "r"(b[1]));
}

// Vectorized fp32 global reduction (sm_90+), no return value.
__device__ __forceinline__ void red2(float* addr, float x, float y) {
    asm volatile("red.global.add.v2.f32 [%0], {%1, %2};"
        :: "l"(addr), "f"(x), "f"(y) : "memory");
}

__device__ __forceinline__ uint32_t pack2(float x, float y) {
    __half2 h = __floats2half2_rn(x, y);
    return *reinterpret_cast<uint32_t*>(&h);
}

// ---------------------------------------------------------------------------
// Per-thread fragment addressing (precomputed outside K loop)
// A tile: [BM][64] halves, 128B rows, 16B-unit swizzle u^=(row&7).
// B tile: [BK][128] halves, 256B rows, swizzle per 128B half.
// ---------------------------------------------------------------------------
struct Frag {
    int aRow[4];
    int aMask[4];
    int hi;
    int bOff[2];
    int g, tig, wm, wn;
};

__device__ __forceinline__ Frag make_frag(int tid) {
    Frag f;
    const int l = tid & 31, wid = tid >> 5;
    f.wm = (wid >> 2) * 64;
    f.wn = (wid & 3) * 32;
    f.g = l >> 2; f.tig = l & 3;
    f.hi = l >> 4;
    const int low8 = l & 7, seg8 = (l >> 3) & 1;
#pragma unroll
    for (int mi = 0; mi < 4; ++mi) {
        const int rA = f.wm + 16 * mi + low8 + 8 * seg8;
        f.aRow[mi] = rA * 128;
        f.aMask[mi] = rA & 7;
    }
#pragma unroll
    for (int p = 0; p < 2; ++p) {
        const int uB = (f.wn >> 3) + 2 * p + f.hi;
        f.bOff[p] = (l & 15) * 256 + ((uB >> 3) << 7) + ((((uB & 7) ^ low8)) << 4);
    }
    return f;
}

// Software-pipelined stage (k-step fragments prefetched one step ahead).
__device__ __forceinline__ void compute_stage(uint32_t As, uint32_t Bs,
                                              const Frag& f, float c[4][4][4]) {
    uint32_t a[2][4][4], rb[2][2][4];
#pragma unroll
    for (int mi = 0; mi < 4; ++mi)
        ldsm4(a[0][mi], As + f.aRow[mi] + ((f.hi ^ f.aMask[mi]) << 4));
#pragma unroll
    for (int p = 0; p < 2; ++p)
        ldsm4t(rb[0][p], Bs + f.bOff[p]);

#pragma unroll
    for (int ks = 0; ks < 4; ++ks) {
        const int cur = ks & 1, nxt = cur ^ 1;
        if (ks < 3) {
            const int kkU = 2 * (ks + 1);
#pragma unroll
            for (int mi = 0; mi < 4; ++mi)
                ldsm4(a[nxt][mi], As + f.aRow[mi] + (((kkU + f.hi) ^ f.aMask[mi]) << 4));
#pragma unroll
            for (int p = 0; p < 2; ++p)
                ldsm4t(rb[nxt][p], Bs + (16 * (ks + 1)) * 256 + f.bOff[p]);
        }
#pragma unroll
        for (int mi = 0; mi < 4; ++mi)
#pragma unroll
            for (int p = 0; p < 2; ++p) {
                mma16(c[mi][2 * p + 0], a[cur][mi], &rb[cur][p][0]);
                mma16(c[mi][2 * p + 1], a[cur][mi], &rb[cur][p][2]);
            }
    }
}

// cp.async destination offsets (byte), swizzled
__device__ __forceinline__ uint32_t a_dst(int row, int u) {        // u 0..7
    return (uint32_t)(row * 128 + ((u ^ (row & 7)) << 4));
}
__device__ __forceinline__ uint32_t b_dst(int row, int u) {        // u 0..15
    return (uint32_t)(row * 256 + ((u >> 3) << 7) + ((((u & 7) ^ (row & 7))) << 4));
}

// ---------------------------------------------------------------------------
// Pre-pass kernels (simple one-load form — measured faster than MLP-batched)
// ---------------------------------------------------------------------------
__device__ __forceinline__ void conv8(const float* src, uint4* dst) {
    const float4 a = *(const float4*)(src);
    const float4 b = *(const float4*)(src + 4);
    uint4 o;
    o.x = pack2(a.x, a.y); o.y = pack2(a.z, a.w);
    o.z = pack2(b.x, b.y); o.w = pack2(b.z, b.w);
    *dst = o;
}
__global__ __launch_bounds__(256) void prep_X(const float* __restrict__ X) {
    const size_t i = (size_t)blockIdx.x * 256 + threadIdx.x;
    conv8(X + i * 8, g_Xh + i);
}
// Wgu: interleave gate/up columns. Output col 2j = orig col j (gate),
// output col 2j+1 = orig col j+kF (up).
__global__ __launch_bounds__(256) void prep_Wgu(const float* __restrict__ W) {
    const size_t i = (size_t)blockIdx.x * 256 + threadIdx.x;  // over E*D*2F/8
    constexpr int NG = k2F / 8;                               // 192 groups/row
    const int grp = (int)(i % NG);
    const size_t row = i / NG;
    const float* src = W + row * k2F;
    const int j0 = grp * 4;
    const float4 gt = *(const float4*)(src + j0);
    const float4 up = *(const float4*)(src + kF + j0);
    uint4 o;
    o.x = pack2(gt.x, up.x); o.y = pack2(gt.y, up.y);
    o.z = pack2(gt.z, up.z); o.w = pack2(gt.w, up.w);
    g_Wguh[i] = o;
}
__global__ __launch_bounds__(256) void prep_Wd(const float* __restrict__ W) {
    const size_t i = (size_t)blockIdx.x * 256 + threadIdx.x;
    conv8(W + i * 8, g_Wdh + i);
}

// Zero the output (atomic reduction target must start at 0; d_out is poisoned).
__global__ __launch_bounds__(256) void zero_out(float* __restrict__ Out) {
    const size_t i4 = ((size_t)blockIdx.x * 256 + threadIdx.x) * 4;
    *(float4*)(Out + i4) = make_float4(0.0f, 0.0f, 0.0f, 0.0f);
}

// ---------------------------------------------------------------------------
// GEMM1 (fused): C = Xh @ Wguh (gate/up interleaved cols); epilogue computes
// fp16(rw*up*silu(gate)), stages through smem, stores coalesced 16B chunks.
// grid (16, 12, 32), 256 threads, 32 K-iters of BK=64.
// ---------------------------------------------------------------------------
constexpr int EP_LD = 72;   // halves per staging row (144B; pad kills bank alias)

__global__ __launch_bounds__(NTHREADS, 2)
void moe_gemm1(const float* __restrict__ RW) {
    extern __shared__ char smem[];
    const int tid = threadIdx.x;
    const int m0 = blockIdx.x * BM, n0 = blockIdx.y * BN, e = blockIdx.z;
    const uint32_t sb = smem_u32(smem);

    const __half* Xh = (const __half*)g_Xh;
    const __half* We = (const __half*)g_Wguh + (size_t)e * kD * k2F;

    const int arow = tid >> 1, au = (tid & 1) * 4;
    const int brow = tid >> 2, bu = (tid & 3) * 4;
    const __half* gA = Xh + (size_t)(m0 + arow) * kD + au * 8;
    const __half* gB = We + (size_t)brow * k2F + n0 + bu * 8;

    uint32_t aD[4], bD[4];
#pragma unroll
    for (int q = 0; q < 4; ++q) {
        aD[q] = a_dst(arow, au + q);
        bD[q] = b_dst(brow, bu + q);
    }

    const Frag f = make_frag(tid);
    float c[4][4][4];
#pragma unroll
    for (int i = 0; i < 4; ++i)
#pragma unroll
        for (int j = 0; j < 4; ++j)
#pragma unroll
            for (int q = 0; q < 4; ++q) c[i][j][q] = 0.0f;

    constexpr int ITERS = kD / BK;   // 32

    auto issue = [&](int it) {
        const uint32_t st = sb + (it % STAGES) * STAGE_BYTES;
        const int k0 = it * BK;
#pragma unroll
        for (int q = 0; q < 4; ++q)
            cp16(st + aD[q], gA + k0 + q * 8);
#pragma unroll
        for (int q = 0; q < 4; ++q)
            cp16(st + A_BYTES + bD[q], gB + (size_t)k0 * k2F + q * 8);
    };

    issue(0); CP_COMMIT();
    issue(1); CP_COMMIT();

    for (int it = 0; it < ITERS; ++it) {
        CP_WAIT1();
        __syncthreads();
        if (it + 2 < ITERS) issue(it + 2);
        CP_COMMIT();
        const uint32_t st = sb + (it % STAGES) * STAGE_BYTES;
        compute_stage(st, st + A_BYTES, f, c);
    }

    // ---- Fused epilogue, smem-staged for coalesced stores ----
    __syncthreads();
    __half* s_ep = (__half*)smem;            // [128 rows][EP_LD halves]
#pragma unroll
    for (int mi = 0; mi < 4; ++mi) {
        const int row0 = f.wm + 16 * mi + f.g;
        const int row1 = row0 + 8;
        const float rw0 = RW[(size_t)(m0 + row0) * kE + e];
        const float rw1 = RW[(size_t)(m0 + row1) * kE + e];
#pragma unroll
        for (int nj = 0; nj < 4; ++nj) {
            const int fl = (f.wn >> 1) + 4 * nj + f.tig;
            const float gt0 = c[mi][nj][0], up0 = c[mi][nj][1];
            const float gt1 = c[mi][nj][2], up1 = c[mi][nj][3];
            s_ep[row0 * EP_LD + fl] =
                __float2half_rn(rw0 * up0 * (gt0 / (1.0f + __expf(-gt0))));
            s_ep[row1 * EP_LD + fl] =
                __float2half_rn(rw1 * up1 * (gt1 / (1.0f + __expf(-gt1))));
        }
    }
    __syncthreads();

    const int erow = tid >> 1, eseg = (tid & 1) * 32;
    const int f0 = n0 >> 1;
    const uint4* src = (const uint4*)(s_ep + erow * EP_LD + eseg);
    uint4* dst = (uint4*)((__half*)g_gatedh +
                          ((size_t)e * kT + m0 + erow) * kF + f0 + eseg);
#pragma unroll
    for (int q = 0; q < 4; ++q) dst[q] = src[q];
}

// ---------------------------------------------------------------------------
// GEMM2 (split-K x8 over experts): z handles experts [4z, 4z+4); epilogue
// reduces directly into Out via red.global.add.v2.f32 (Out pre-zeroed).
// grid (16, 16, 8), 256 threads, 48 K-iters of BK=64.
// ---------------------------------------------------------------------------
__global__ __launch_bounds__(NTHREADS, 2)
void moe_gemm2(float* __restrict__ Out) {
    extern __shared__ char smem[];
    const int tid = threadIdx.x;
    const int m0 = blockIdx.x * BM, n0 = blockIdx.y * BN;
    const int ez = blockIdx.z * (kE / KSPLIT);
    const uint32_t sb = smem_u32(smem);

    const __half* Ah = (const __half*)g_gatedh;
    const __half* Wh = (const __half*)g_Wdh;

    const int arow = tid >> 1, au = (tid & 1) * 4;
    const int brow = tid >> 2, bu = (tid & 3) * 4;

    uint32_t aD[4], bD[4];
#pragma unroll
    for (int q = 0; q < 4; ++q) {
        aD[q] = a_dst(arow, au + q);
        bD[q] = b_dst(brow, bu + q);
    }

    const Frag f = make_frag(tid);
    float c[4][4][4];
#pragma unroll
    for (int i = 0; i < 4; ++i)
#pragma unroll
        for (int j = 0; j < 4; ++j)
#pragma unroll
            for (int q = 0; q < 4; ++q) c[i][j][q] = 0.0f;

    constexpr int IPEX  = kF / BK;                       // 12
    constexpr int ITERS = (kE / KSPLIT) * IPEX;          // 48

    auto issue = [&](int it) {
        const uint32_t st = sb + (it % STAGES) * STAGE_BYTES;
        const int e   = ez + it / IPEX;
        const int kin = (it % IPEX) * BK;
        const __half* gA = Ah + ((size_t)e * kT + m0 + arow) * kF + kin + au * 8;
        const __half* gB = Wh + ((size_t)e * kF + kin + brow) * kD + n0 + bu * 8;
#pragma unroll
        for (int q = 0; q < 4; ++q)
            cp16(st + aD[q], gA + q * 8);
#pragma unroll
        for (int q = 0; q < 4; ++q)
            cp16(st + A_BYTES + bD[q], gB + q * 8);
    };

    issue(0); CP_COMMIT();
    issue(1); CP_COMMIT();

    for (int it = 0; it < ITERS; ++it) {
        CP_WAIT1();
        __syncthreads();
        if (it + 2 < ITERS) issue(it + 2);
        CP_COMMIT();
        const uint32_t st = sb + (it % STAGES) * STAGE_BYTES;
        compute_stage(st, st + A_BYTES, f, c);
    }

    // Epilogue: atomic-reduce partial tile straight into Out.
    float* Cp = Out + (size_t)m0 * kD + n0;
#pragma unroll
    for (int mi = 0; mi < 4; ++mi)
#pragma unroll
        for (int nj = 0; nj < 4; ++nj) {
            const int r0 = f.wm + 16 * mi + f.g;
            const int cc = f.wn + 8 * nj + 2 * f.tig;
            red2(Cp + (size_t)r0 * kD + cc,       c[mi][nj][0], c[mi][nj][1]);
            red2(Cp + (size_t)(r0 + 8) * kD + cc, c[mi][nj][2], c[mi][nj][3]);
        }
}

// ---------------------------------------------------------------------------
// kernel_launch
//   0: hidden_states fp32 [T,D]   1: routing_weights fp32 [T,E]
//   2: router_indices (unused)    3: gate_up_proj fp32 [E,D,2F]
//   4: down_proj fp32 [E,F,D]     out: fp32 [T,D]
// ---------------------------------------------------------------------------
extern "C" void kernel_launch(void* const* d_in, const int* in_sizes, int n_in,
                              void* d_out, int out_size)
{
    const float* X   = (const float*)d_in[0];
    const float* RW  = (const float*)d_in[1];
    const float* Wgu = (const float*)d_in[3];
    const float* Wdn = (const float*)d_in[4];
    float* Out = (float*)d_out;

    cudaFuncSetAttribute(moe_gemm1, cudaFuncAttributeMaxDynamicSharedMemorySize, SMEM_BYTES);
    cudaFuncSetAttribute(moe_gemm2, cudaFuncAttributeMaxDynamicSharedMemorySize, SMEM_BYTES);

    prep_X<<<(int)(((size_t)kT * kD / 8) / 256), 256>>>(X);                    // 2048
    prep_Wgu<<<(int)(((size_t)kE * kD * k2F / 8) / 256), 256>>>(Wgu);          // 49152
    prep_Wd<<<(int)(((size_t)kE * kF * kD / 8) / 256), 256>>>(Wdn);            // 24576
    zero_out<<<(int)(((size_t)kT * kD / 4) / 256), 256>>>(Out);                // 4096

    moe_gemm1<<<dim3(kT / BM, k2F / BN, kE), NTHREADS, SMEM_BYTES>>>(RW);      // (16,12,32)

    moe_gemm2<<<dim3(kT / BM, kD / BN, KSPLIT), NTHREADS, SMEM_BYTES>>>(Out);  // (16,16,8)
}